// round 2
// baseline (speedup 1.0000x reference)
#include <cuda_runtime.h>
#include <cuda_bf16.h>

// Grouped rational activation:
//   out = P(z) / Q(z),  P degree 5 (6 coeffs, shared across groups),
//   Q(z) = 1 + |b1| z + |b2| z^2 + |b3| z^3 + |b4| z^4  (per-group b's)
// Shapes: x (4, 4096, 2048) fp32, G=8 groups, Dpg=256.
// Memory-bound pointwise. 2x float4 per thread, stride n4/2 (same group for
// both elements since n4/2 is a multiple of 512 = float4s per D-row).

#define D_TOTAL     2048
#define GROUPS      8
#define F4_PER_ROW  (D_TOTAL / 4)        // 512
#define F4_PER_GRP  (D_TOTAL / GROUPS / 4) // 64

__global__ __launch_bounds__(256)
void kat_group_kernel(const float4* __restrict__ x,
                      const float4* __restrict__ wnum4,  // 6 floats: float4 + float2
                      const float4* __restrict__ wden4,  // (8,4) -> 8 float4 rows
                      float4* __restrict__ out,
                      int n4h)                            // n4 / 2
{
    int i = blockIdx.x * blockDim.x + threadIdx.x;
    if (i >= n4h) return;
    int j = i + n4h;

    // group of this float4 (identical for i and j: n4h % 512 == 0)
    int g = (i >> 6) & (GROUPS - 1);   // (i & 511) / 64

    // front-batch the two data loads (MLP)
    float4 v0 = x[i];
    float4 v1 = x[j];

    // numerator coeffs: one float4 + one float2 (L1-resident)
    float4 aa = __ldg(wnum4);
    float2 ab = __ldg((const float2*)(wnum4) + 2);
    float a0 = aa.x, a1 = aa.y, a2 = aa.z, a3 = aa.w, a4 = ab.x, a5 = ab.y;

    // denominator coeffs for this group: c0=1, c1..c4 = |b1..b4|
    float4 bb = __ldg(wden4 + g);
    float c1 = fabsf(bb.x), c2 = fabsf(bb.y), c3 = fabsf(bb.z), c4 = fabsf(bb.w);

    float zs[8] = {v0.x, v0.y, v0.z, v0.w, v1.x, v1.y, v1.z, v1.w};
    float os[8];

    #pragma unroll
    for (int k = 0; k < 8; ++k) {
        float z = zs[k];

        // numerator Horner, degree 5
        float p = fmaf(a5, z, a4);
        p = fmaf(p, z, a3);
        p = fmaf(p, z, a2);
        p = fmaf(p, z, a1);
        p = fmaf(p, z, a0);

        // denominator Horner, degree 4, c0 = 1
        float q = fmaf(c4, z, c3);
        q = fmaf(q, z, c2);
        q = fmaf(q, z, c1);
        q = fmaf(q, z, 1.0f);

        os[k] = __fdividef(p, q);
    }

    float4 r0 = make_float4(os[0], os[1], os[2], os[3]);
    float4 r1 = make_float4(os[4], os[5], os[6], os[7]);
    out[i] = r0;
    out[j] = r1;
}

extern "C" void kernel_launch(void* const* d_in, const int* in_sizes, int n_in,
                              void* d_out, int out_size)
{
    const float* x    = (const float*)d_in[0];
    const float* wnum = (const float*)d_in[1];
    const float* wden = (const float*)d_in[2];
    // d_in[3] = num_groups (int32 on device) — fixed at 8 for this problem

    int n   = in_sizes[0];   // 33_554_432 floats
    int n4h = n / 8;         // 4_194_304 (pairs of float4)

    int threads = 256;
    int blocks  = (n4h + threads - 1) / threads;

    kat_group_kernel<<<blocks, threads>>>(
        (const float4*)x, (const float4*)wnum, (const float4*)wden,
        (float4*)d_out, n4h);
}